// round 2
// baseline (speedup 1.0000x reference)
#include <cuda_runtime.h>
#include <math.h>

#define BB     1024
#define HH     256
#define FOURH  1024
#define LAT    128
#define ROWS   8
#define NCTA   (BB / ROWS)      // 128 CTAs
#define NT     256              // threads per CTA, thread t owns H-column j=t
#define GSIZE  64               // group size for GroupNorm (256/4)
#define EPSG   1e-5f

// -------- device scratch (allocation-free rule: __device__ globals) --------
// Gate-interleaved, k-major transposed weights: element [k][j] is a float4
// holding W[(g*H+j), k] for g = i,f,g,o.
__device__ float4 g_Wt0 [HH * HH];   // Whh0^T
__device__ float4 g_Wt1i[HH * HH];   // Wih1^T
__device__ float4 g_Wt1h[HH * HH];   // Whh1^T
__device__ float  g_Wut [LAT * HH];  // W_unpack^T  [k][j]

__device__ __forceinline__ float tanh_fast(float x) {
    float y;
    asm("tanh.approx.f32 %0, %1;" : "=f"(y) : "f"(x));
    return y;
}
__device__ __forceinline__ float sig_fast(float x) {
    return 0.5f * tanh_fast(0.5f * x) + 0.5f;
}

// -------- prologue: transpose weights into k-major gate-interleaved layout ----
__global__ void prep_kernel(const float* __restrict__ Whh0,
                            const float* __restrict__ Wih1,
                            const float* __restrict__ Whh1,
                            const float* __restrict__ Wu) {
    int i = blockIdx.x * blockDim.x + threadIdx.x;
    if (i < HH * FOURH) {
        int k   = i >> 10;          // / 1024
        int rem = i & 1023;
        int j   = rem >> 2;
        int g   = rem & 3;
        int src = (g * HH + j) * HH + k;   // row n = g*256+j, col k of (1024,256)
        ((float*)g_Wt0)[i]  = Whh0[src];
        ((float*)g_Wt1i)[i] = Wih1[src];
        ((float*)g_Wt1h)[i] = Whh1[src];
    }
    if (i < LAT * HH) {
        int k = i >> 8, j = i & 255;       // W_unpack is (256,128)
        g_Wut[i] = Wu[j * LAT + k];
    }
}

// -------- main persistent kernel: 8 batch rows per CTA, full recurrence ------
__global__ __launch_bounds__(NT, 1)
void gen_kernel(const float* __restrict__ noise,
                const float* __restrict__ b_unpack,
                const float* __restrict__ Wih0,
                const float* __restrict__ bih0, const float* __restrict__ bhh0,
                const float* __restrict__ bih1, const float* __restrict__ bhh1,
                const float* __restrict__ gamma_a, const float* __restrict__ beta_a,
                const float* __restrict__ Wa, const float* __restrict__ ba,
                const float* __restrict__ gamma_w, const float* __restrict__ beta_w,
                const float* __restrict__ Ww, const float* __restrict__ bw,
                int T, float* __restrict__ out) {
    __shared__ __align__(16) float sh0[ROWS][HH];
    __shared__ __align__(16) float sh1[ROWS][HH];
    __shared__ float snoise[ROWS][LAT];
    __shared__ float sGA[HH], sBA[HH], sGW[HH], sBW[HH];
    __shared__ float sStat[ROWS][4][2];     // [row][group][mu, rstd]
    __shared__ float scoord[ROWS][2];

    const int t    = threadIdx.x;           // H-column this thread owns
    const int r0   = blockIdx.x * ROWS;
    const int warp = t >> 5;
    const int lane = t & 31;

    // Head constants folded: contribution of column j is (xn*gamma+beta)*W
    {
        float wav = Wa[t], wwv = Ww[t];
        sGA[t] = gamma_a[t] * wav;  sBA[t] = beta_a[t] * wav;
        sGW[t] = gamma_w[t] * wwv;  sBW[t] = beta_w[t] * wwv;
    }
    const float bav = ba[0], bwv = bw[0];

    // Per-thread gate constants (4 gates for column t)
    float bias0[4], bias1[4], wi0a[4], wi0b[4];
#pragma unroll
    for (int g = 0; g < 4; g++) {
        int n = g * HH + t;
        bias0[g] = bih0[n] + bhh0[n];
        bias1[g] = bih1[n] + bhh1[n];
        wi0a[g]  = Wih0[n * 2 + 0];
        wi0b[g]  = Wih0[n * 2 + 1];
    }

    // Stage noise rows
    for (int i = t; i < ROWS * LAT; i += NT)
        ((float*)snoise)[i] = noise[(size_t)r0 * LAT + i];
    if (t < ROWS * 2) ((float*)scoord)[t] = 0.f;
    __syncthreads();

    // idea = elu(noise @ W_unpack^T + b_unpack); h0=c0=idea, h1=c1=0
    float c0r[ROWS], c1r[ROWS];
    {
        float acc[ROWS];
        float bu = b_unpack[t];
#pragma unroll
        for (int r = 0; r < ROWS; r++) acc[r] = bu;
        for (int k = 0; k < LAT; k++) {
            float w = g_Wut[k * HH + t];
#pragma unroll
            for (int r = 0; r < ROWS; r++) acc[r] = fmaf(snoise[r][k], w, acc[r]);
        }
#pragma unroll
        for (int r = 0; r < ROWS; r++) {
            float v = acc[r];
            float e = (v > 0.f) ? v : (expf(v) - 1.f);
            sh0[r][t] = e;  c0r[r] = e;
            sh1[r][t] = 0.f; c1r[r] = 0.f;
        }
    }
    __syncthreads();

    const float4* __restrict__ w0  = g_Wt0  + t;
    const float4* __restrict__ w1i = g_Wt1i + t;
    const float4* __restrict__ w1h = g_Wt1h + t;

    for (int step = 0; step < T; ++step) {
        // ======== layer 0: gates = h0 @ Whh0^T + coords @ Wih0^T + bias ========
        float acc[4][ROWS];
#pragma unroll
        for (int g = 0; g < 4; g++)
#pragma unroll
            for (int r = 0; r < ROWS; r++)
                acc[g][r] = fmaf(wi0a[g], scoord[r][0],
                           fmaf(wi0b[g], scoord[r][1], bias0[g]));
#pragma unroll 4
        for (int k = 0; k < HH; k++) {
            float4 w = __ldg(&w0[k * HH]);
#pragma unroll
            for (int r = 0; r < ROWS; r++) {
                float hv = sh0[r][k];
                acc[0][r] = fmaf(w.x, hv, acc[0][r]);
                acc[1][r] = fmaf(w.y, hv, acc[1][r]);
                acc[2][r] = fmaf(w.z, hv, acc[2][r]);
                acc[3][r] = fmaf(w.w, hv, acc[3][r]);
            }
        }
        float h0new[ROWS];
#pragma unroll
        for (int r = 0; r < ROWS; r++) {
            float ig = sig_fast(acc[0][r]);
            float fg = sig_fast(acc[1][r]);
            float gg = tanh_fast(acc[2][r]);
            float og = sig_fast(acc[3][r]);
            float cn = fmaf(fg, c0r[r], ig * gg);
            c0r[r]   = cn;
            h0new[r] = og * tanh_fast(cn);
        }
        __syncthreads();                       // everyone done reading old sh0
#pragma unroll
        for (int r = 0; r < ROWS; r++) sh0[r][t] = h0new[r];
        __syncthreads();

        // ======== layer 1: gates = h0_new @ Wih1^T + h1 @ Whh1^T + bias ========
#pragma unroll
        for (int g = 0; g < 4; g++)
#pragma unroll
            for (int r = 0; r < ROWS; r++) acc[g][r] = bias1[g];
#pragma unroll 2
        for (int k = 0; k < HH; k++) {
            float4 wi = __ldg(&w1i[k * HH]);
            float4 wh = __ldg(&w1h[k * HH]);
#pragma unroll
            for (int r = 0; r < ROWS; r++) {
                float a = sh0[r][k];
                float b = sh1[r][k];
                acc[0][r] = fmaf(wi.x, a, fmaf(wh.x, b, acc[0][r]));
                acc[1][r] = fmaf(wi.y, a, fmaf(wh.y, b, acc[1][r]));
                acc[2][r] = fmaf(wi.z, a, fmaf(wh.z, b, acc[2][r]));
                acc[3][r] = fmaf(wi.w, a, fmaf(wh.w, b, acc[3][r]));
            }
        }
        float h1new[ROWS];
#pragma unroll
        for (int r = 0; r < ROWS; r++) {
            float ig = sig_fast(acc[0][r]);
            float fg = sig_fast(acc[1][r]);
            float gg = tanh_fast(acc[2][r]);
            float og = sig_fast(acc[3][r]);
            float cn = fmaf(fg, c1r[r], ig * gg);
            c1r[r]   = cn;
            h1new[r] = og * tanh_fast(cn);
        }
        __syncthreads();                       // everyone done reading old sh1
#pragma unroll
        for (int r = 0; r < ROWS; r++) sh1[r][t] = h1new[r];
        __syncthreads();

        // ======== GroupNorm stats: warp w handles row w ========
        {
            int r = warp;
#pragma unroll
            for (int g = 0; g < 4; g++) {
                float v0 = sh1[r][g * GSIZE + lane];
                float v1 = sh1[r][g * GSIZE + 32 + lane];
                float s = v0 + v1, q = fmaf(v0, v0, v1 * v1);
#pragma unroll
                for (int off = 16; off; off >>= 1) {
                    s += __shfl_xor_sync(0xffffffffu, s, off);
                    q += __shfl_xor_sync(0xffffffffu, q, off);
                }
                if (lane == 0) {
                    float mu  = s * (1.f / GSIZE);
                    float var = q * (1.f / GSIZE) - mu * mu;
                    sStat[r][g][0] = mu;
                    sStat[r][g][1] = rsqrtf(var + EPSG);
                }
            }
        }
        __syncthreads();

        // ======== heads: angle = tanh(gn_a(h1)@Wa+ba), width = sig(gn_w(h1)@Ww+bw)
        {
            int r = warp;
            float aacc = 0.f, wacc = 0.f;
#pragma unroll
            for (int jj = 0; jj < HH; jj += 32) {
                int j = jj + lane;
                int g = jj >> 6;               // uniform per iteration
                float xn = (sh1[r][j] - sStat[r][g][0]) * sStat[r][g][1];
                aacc += fmaf(xn, sGA[j], sBA[j]);
                wacc += fmaf(xn, sGW[j], sBW[j]);
            }
#pragma unroll
            for (int off = 16; off; off >>= 1) {
                aacc += __shfl_xor_sync(0xffffffffu, aacc, off);
                wacc += __shfl_xor_sync(0xffffffffu, wacc, off);
            }
            if (lane == 0) {
                float ang = tanh_fast(aacc + bav);
                float wid = sig_fast(wacc + bwv);
                scoord[r][0] = ang;
                scoord[r][1] = wid;
                float2* op = (float2*)(out + ((size_t)(r0 + r) * T + step) * 2);
                *op = make_float2(ang, wid);
            }
        }
        __syncthreads();                       // coords visible for next step
    }
}

extern "C" void kernel_launch(void* const* d_in, const int* in_sizes, int n_in,
                              void* d_out, int out_size) {
    const float* noise    = (const float*)d_in[0];
    const float* W_unpack = (const float*)d_in[1];
    const float* b_unpack = (const float*)d_in[2];
    const float* Wih0     = (const float*)d_in[3];
    const float* Whh0     = (const float*)d_in[4];
    const float* bih0     = (const float*)d_in[5];
    const float* bhh0     = (const float*)d_in[6];
    const float* Wih1     = (const float*)d_in[7];
    const float* Whh1     = (const float*)d_in[8];
    const float* bih1     = (const float*)d_in[9];
    const float* bhh1     = (const float*)d_in[10];
    const float* gamma_a  = (const float*)d_in[11];
    const float* beta_a   = (const float*)d_in[12];
    const float* Wa       = (const float*)d_in[13];
    const float* ba       = (const float*)d_in[14];
    const float* gamma_w  = (const float*)d_in[15];
    const float* beta_w   = (const float*)d_in[16];
    const float* Ww       = (const float*)d_in[17];
    const float* bw       = (const float*)d_in[18];
    (void)in_sizes; (void)n_in;

    // T derived host-side from output size: out is (B, T, 2) float32
    int T = out_size / (BB * 2);

    prep_kernel<<<(HH * FOURH + 255) / 256, 256>>>(Whh0, Wih1, Whh1, W_unpack);
    gen_kernel<<<NCTA, NT>>>(noise, b_unpack, Wih0, bih0, bhh0, bih1, bhh1,
                             gamma_a, beta_a, Wa, ba, gamma_w, beta_w, Ww, bw,
                             T, (float*)d_out);
}